// round 1
// baseline (speedup 1.0000x reference)
#include <cuda_runtime.h>
#include <math.h>

#define Bn 4
#define Sn 2048
#define Dn 1024
#define Hn 16
#define DHn 64
#define Mn (Bn * Sn)   // 8192

// Scratch (device globals — no allocation allowed in kernel_launch)
__device__ float g_Q[Mn * Dn];
__device__ float g_K[Mn * Dn];
__device__ float g_V[Mn * Dn];
__device__ float g_AV[Mn * Dn];
__device__ float g_AO[Mn * Dn];

// ---------------------------------------------------------------------------
// SGEMM: C[M,N] = A[M,K] @ B[K,N], all row-major. 128x128 tile, BK=8,
// 256 threads, 8x8 per-thread register block.
// ---------------------------------------------------------------------------
__global__ __launch_bounds__(256) void sgemm128(
    const float* __restrict__ A, const float* __restrict__ B,
    float* __restrict__ C, int M, int N, int K)
{
    __shared__ float As[8][128];   // transposed A tile: As[k][m]
    __shared__ float Bs[8][128];   // Bs[k][n]

    const int tid = threadIdx.x;
    const int bx = blockIdx.x, by = blockIdx.y;
    const int tr = tid >> 4, tc = tid & 15;

    float acc[8][8];
#pragma unroll
    for (int i = 0; i < 8; i++)
#pragma unroll
        for (int j = 0; j < 8; j++) acc[i][j] = 0.f;

    const int arow = tid >> 1;          // 0..127
    const int acol = (tid & 1) << 2;    // 0 or 4
    const int brow = tid >> 5;          // 0..7
    const int bcol = (tid & 31) << 2;   // 0..124
    const float* Ag = A + (by * 128 + arow) * K + acol;
    const float* Bg = B + brow * N + bx * 128 + bcol;

    for (int kt = 0; kt < K; kt += 8) {
        float4 a4 = *(const float4*)(Ag + kt);
        As[acol + 0][arow] = a4.x;
        As[acol + 1][arow] = a4.y;
        As[acol + 2][arow] = a4.z;
        As[acol + 3][arow] = a4.w;
        *(float4*)(&Bs[brow][bcol]) = *(const float4*)(Bg + kt * N);
        __syncthreads();
#pragma unroll
        for (int k = 0; k < 8; k++) {
            float a[8], b[8];
            *(float4*)(a)     = *(const float4*)(&As[k][tr * 8]);
            *(float4*)(a + 4) = *(const float4*)(&As[k][tr * 8 + 4]);
            *(float4*)(b)     = *(const float4*)(&Bs[k][tc * 8]);
            *(float4*)(b + 4) = *(const float4*)(&Bs[k][tc * 8 + 4]);
#pragma unroll
            for (int i = 0; i < 8; i++)
#pragma unroll
                for (int j = 0; j < 8; j++)
                    acc[i][j] = fmaf(a[i], b[j], acc[i][j]);
        }
        __syncthreads();
    }

    float* Cp = C + (by * 128 + tr * 8) * N + bx * 128 + tc * 8;
#pragma unroll
    for (int i = 0; i < 8; i++) {
        *(float4*)(Cp + i * N)     = make_float4(acc[i][0], acc[i][1], acc[i][2], acc[i][3]);
        *(float4*)(Cp + i * N + 4) = make_float4(acc[i][4], acc[i][5], acc[i][6], acc[i][7]);
    }
}

// ---------------------------------------------------------------------------
// Flash attention, fp32. One block per (query-tile of 64, head, batch).
// 256 threads. K tile stored transposed in smem (KsT[d][k]) so the QK^T
// microkernel reads rows (conflict-free) instead of strided columns.
// Online softmax state (m, l) replicated in registers across the 16 lanes
// that share a row group — no smem races, shfl reductions only.
// ---------------------------------------------------------------------------
#define PAD 68
__global__ __launch_bounds__(256) void flash_attn()
{
    extern __shared__ float sm[];
    float (*Qs)[PAD]  = (float(*)[PAD])(sm);                 // [64][68] q rows (pre-scaled)
    float (*KsT)[PAD] = (float(*)[PAD])(sm + 64 * PAD);      // [64][68] row=d, col=k
    float (*Vs)[PAD]  = (float(*)[PAD])(sm + 2 * 64 * PAD);  // [64][68] row=k, col=d
    float (*Ps)[PAD]  = (float(*)[PAD])(sm + 3 * 64 * PAD);  // [64][68] probs

    const int tid = threadIdx.x;
    const int qt = blockIdx.x, hh = blockIdx.y, bb = blockIdx.z;
    const int tr = tid >> 4, tc = tid & 15;
    const int tr4 = tr * 4, tc4 = tc * 4;

    const int lr = tid >> 2;          // 0..63 (load row)
    const int lc = (tid & 3) << 4;    // 0,16,32,48

    const float scale = 0.125f;       // 1/sqrt(64)

    // Load Q tile, pre-scaled
    {
        const float* qg = g_Q + (bb * Sn + qt * 64 + lr) * Dn + hh * 64 + lc;
#pragma unroll
        for (int m = 0; m < 4; m++) {
            float4 v4 = *(const float4*)(qg + m * 4);
            Qs[lr][lc + m * 4 + 0] = v4.x * scale;
            Qs[lr][lc + m * 4 + 1] = v4.y * scale;
            Qs[lr][lc + m * 4 + 2] = v4.z * scale;
            Qs[lr][lc + m * 4 + 3] = v4.w * scale;
        }
    }

    float m_run[4], l_run[4], o[4][4];
#pragma unroll
    for (int i = 0; i < 4; i++) {
        m_run[i] = -1e30f;
        l_run[i] = 0.f;
#pragma unroll
        for (int j = 0; j < 4; j++) o[i][j] = 0.f;
    }

    for (int kt = 0; kt < Sn / 64; kt++) {
        // Load K (transposed into smem) and V tiles
        {
            const float* kg = g_K + (bb * Sn + kt * 64 + lr) * Dn + hh * 64 + lc;
#pragma unroll
            for (int m = 0; m < 4; m++) {
                float4 v4 = *(const float4*)(kg + m * 4);
                KsT[lc + m * 4 + 0][lr] = v4.x;
                KsT[lc + m * 4 + 1][lr] = v4.y;
                KsT[lc + m * 4 + 2][lr] = v4.z;
                KsT[lc + m * 4 + 3][lr] = v4.w;
            }
            const float* vg = g_V + (bb * Sn + kt * 64 + lr) * Dn + hh * 64 + lc;
#pragma unroll
            for (int m = 0; m < 4; m++)
                *(float4*)(&Vs[lr][lc + m * 4]) = *(const float4*)(vg + m * 4);
        }
        __syncthreads();

        // ---- Stage A: S = Q @ K^T (4x4 per thread) ----
        float s[4][4];
#pragma unroll
        for (int i = 0; i < 4; i++)
#pragma unroll
            for (int j = 0; j < 4; j++) s[i][j] = 0.f;

#pragma unroll 4
        for (int k4 = 0; k4 < 16; k4++) {
            float qa[4][4];
#pragma unroll
            for (int i = 0; i < 4; i++)
                *(float4*)(qa[i]) = *(const float4*)(&Qs[tr4 + i][k4 * 4]);
#pragma unroll
            for (int m = 0; m < 4; m++) {
                float4 kv = *(const float4*)(&KsT[k4 * 4 + m][tc4]);
#pragma unroll
                for (int i = 0; i < 4; i++) {
                    s[i][0] = fmaf(qa[i][m], kv.x, s[i][0]);
                    s[i][1] = fmaf(qa[i][m], kv.y, s[i][1]);
                    s[i][2] = fmaf(qa[i][m], kv.z, s[i][2]);
                    s[i][3] = fmaf(qa[i][m], kv.w, s[i][3]);
                }
            }
        }

        // ---- Online softmax (rows tr4+i, reduce across the 16 tc lanes) ----
        float alpha[4];
#pragma unroll
        for (int i = 0; i < 4; i++) {
            float mx = fmaxf(fmaxf(s[i][0], s[i][1]), fmaxf(s[i][2], s[i][3]));
#pragma unroll
            for (int off = 8; off > 0; off >>= 1)
                mx = fmaxf(mx, __shfl_xor_sync(0xffffffffu, mx, off));
            float mnew = fmaxf(m_run[i], mx);
            alpha[i] = __expf(m_run[i] - mnew);
            m_run[i] = mnew;
            float ls = 0.f;
#pragma unroll
            for (int j = 0; j < 4; j++) {
                s[i][j] = __expf(s[i][j] - mnew);
                ls += s[i][j];
            }
#pragma unroll
            for (int off = 8; off > 0; off >>= 1)
                ls += __shfl_xor_sync(0xffffffffu, ls, off);
            l_run[i] = l_run[i] * alpha[i] + ls;
            *(float4*)(&Ps[tr4 + i][tc4]) = make_float4(s[i][0], s[i][1], s[i][2], s[i][3]);
        }
        // Ps rows for this thread were written entirely by this warp
        __syncwarp(0xffffffffu);

        // ---- Stage B: O = O*alpha + P @ V (4x4 per thread) ----
#pragma unroll
        for (int i = 0; i < 4; i++)
#pragma unroll
            for (int j = 0; j < 4; j++) o[i][j] *= alpha[i];

#pragma unroll 4
        for (int k4 = 0; k4 < 16; k4++) {
            float pa[4][4];
#pragma unroll
            for (int i = 0; i < 4; i++)
                *(float4*)(pa[i]) = *(const float4*)(&Ps[tr4 + i][k4 * 4]);
#pragma unroll
            for (int m = 0; m < 4; m++) {
                float4 vv = *(const float4*)(&Vs[k4 * 4 + m][tc4]);
#pragma unroll
                for (int i = 0; i < 4; i++) {
                    o[i][0] = fmaf(pa[i][m], vv.x, o[i][0]);
                    o[i][1] = fmaf(pa[i][m], vv.y, o[i][1]);
                    o[i][2] = fmaf(pa[i][m], vv.z, o[i][2]);
                    o[i][3] = fmaf(pa[i][m], vv.w, o[i][3]);
                }
            }
        }
        __syncthreads();  // protect Ks/Vs/Ps before next tile's loads/writes
    }

    // Epilogue: normalize and write attn_vec [b, s, h*dh]
#pragma unroll
    for (int i = 0; i < 4; i++) {
        float inv = 1.0f / l_run[i];
        float4 r = make_float4(o[i][0] * inv, o[i][1] * inv, o[i][2] * inv, o[i][3] * inv);
        *(float4*)(g_AV + (bb * Sn + qt * 64 + tr4 + i) * Dn + hh * 64 + tc4) = r;
    }
}

// ---------------------------------------------------------------------------
// Residual + LayerNorm: out = gamma * norm(h + attn_out) + beta.
// One block per row (1024 elems), 256 threads, 4 elems (one float4) each.
// ---------------------------------------------------------------------------
__global__ __launch_bounds__(256) void ln_residual(
    const float* __restrict__ h, const float* __restrict__ gamma,
    const float* __restrict__ beta, float* __restrict__ out)
{
    const int row = blockIdx.x;
    const int tid = threadIdx.x;

    const float4 hv = *(const float4*)(h + row * Dn + tid * 4);
    const float4 av = *(const float4*)(g_AO + row * Dn + tid * 4);
    float4 x = make_float4(hv.x + av.x, hv.y + av.y, hv.z + av.z, hv.w + av.w);

    float s  = x.x + x.y + x.z + x.w;
    float ss = x.x * x.x + x.y * x.y + x.z * x.z + x.w * x.w;
#pragma unroll
    for (int off = 16; off > 0; off >>= 1) {
        s  += __shfl_xor_sync(0xffffffffu, s, off);
        ss += __shfl_xor_sync(0xffffffffu, ss, off);
    }
    __shared__ float rs[8], rss[8];
    if ((tid & 31) == 0) { rs[tid >> 5] = s; rss[tid >> 5] = ss; }
    __syncthreads();
    s = 0.f; ss = 0.f;
#pragma unroll
    for (int w = 0; w < 8; w++) { s += rs[w]; ss += rss[w]; }

    const float mu  = s * (1.0f / Dn);
    const float var = ss * (1.0f / Dn) - mu * mu;
    const float inv = rsqrtf(var + 1e-5f);

    const float4 g4 = *(const float4*)(gamma + tid * 4);
    const float4 b4 = *(const float4*)(beta + tid * 4);
    float4 r;
    r.x = g4.x * (x.x - mu) * inv + b4.x;
    r.y = g4.y * (x.y - mu) * inv + b4.y;
    r.z = g4.z * (x.z - mu) * inv + b4.z;
    r.w = g4.w * (x.w - mu) * inv + b4.w;
    *(float4*)(out + row * Dn + tid * 4) = r;
}

// ---------------------------------------------------------------------------
extern "C" void kernel_launch(void* const* d_in, const int* in_sizes, int n_in,
                              void* d_out, int out_size)
{
    (void)in_sizes; (void)n_in; (void)out_size;
    const float* h     = (const float*)d_in[0];
    const float* Wq    = (const float*)d_in[1];
    const float* Wk    = (const float*)d_in[2];
    const float* Wv    = (const float*)d_in[3];
    const float* Wo    = (const float*)d_in[4];
    const float* gamma = (const float*)d_in[5];
    const float* beta  = (const float*)d_in[6];
    float* out = (float*)d_out;

    float *Qp, *Kp, *Vp, *AVp, *AOp;
    cudaGetSymbolAddress((void**)&Qp,  g_Q);
    cudaGetSymbolAddress((void**)&Kp,  g_K);
    cudaGetSymbolAddress((void**)&Vp,  g_V);
    cudaGetSymbolAddress((void**)&AVp, g_AV);
    cudaGetSymbolAddress((void**)&AOp, g_AO);

    const int flash_smem = 4 * 64 * PAD * (int)sizeof(float);  // 69632 B
    cudaFuncSetAttribute(flash_attn, cudaFuncAttributeMaxDynamicSharedMemorySize,
                         flash_smem);

    dim3 gemm_grid(Dn / 128, Mn / 128);   // (8, 64)
    sgemm128<<<gemm_grid, 256>>>(h, Wq, Qp, Mn, Dn, Dn);
    sgemm128<<<gemm_grid, 256>>>(h, Wk, Kp, Mn, Dn, Dn);
    sgemm128<<<gemm_grid, 256>>>(h, Wv, Vp, Mn, Dn, Dn);

    flash_attn<<<dim3(Sn / 64, Hn, Bn), 256, flash_smem>>>();

    sgemm128<<<gemm_grid, 256>>>(AVp, Wo, AOp, Mn, Dn, Dn);

    ln_residual<<<Mn, 256>>>(h, gamma, beta, out);
}

// round 3
// speedup vs baseline: 1.3433x; 1.3433x over previous
#include <cuda_runtime.h>
#include <cuda_bf16.h>
#include <cstdint>
#include <math.h>

#define Bn 4
#define Sn 2048
#define Dn 1024
#define Hn 16
#define DHn 64
#define Mn (Bn * Sn)   // 8192

// ---------------------------------------------------------------------------
// Device scratch (no allocation allowed in kernel_launch)
// ---------------------------------------------------------------------------
__device__ float g_Q[Mn * Dn];
__device__ float g_K[Mn * Dn];
__device__ float g_V[Mn * Dn];
__device__ float g_AV[Mn * Dn];
__device__ float g_AO[Mn * Dn];

__device__ __nv_bfloat16 g_hA_hi[Mn * Dn];
__device__ __nv_bfloat16 g_hA_lo[Mn * Dn];
__device__ __nv_bfloat16 g_AV_hi[Mn * Dn];
__device__ __nv_bfloat16 g_AV_lo[Mn * Dn];
__device__ __nv_bfloat16 g_W_hi[4 * Dn * Dn];   // transposed [N,K], order q,k,v,o
__device__ __nv_bfloat16 g_W_lo[4 * Dn * Dn];

// ---------------------------------------------------------------------------
__device__ __forceinline__ uint32_t smem_u32(const void* p) {
    uint32_t a;
    asm("{ .reg .u64 t; cvta.to.shared.u64 t, %1; cvt.u32.u64 %0, t; }"
        : "=r"(a) : "l"(p));
    return a;
}

__device__ __forceinline__ void ldm_x4(uint32_t* r, uint32_t addr) {
    asm volatile("ldmatrix.sync.aligned.m8n8.x4.shared.b16 {%0,%1,%2,%3}, [%4];"
                 : "=r"(r[0]), "=r"(r[1]), "=r"(r[2]), "=r"(r[3]) : "r"(addr));
}

__device__ __forceinline__ void mma_bf16(float* c, const uint32_t* a,
                                         uint32_t b0, uint32_t b1) {
    asm volatile(
        "mma.sync.aligned.m16n8k16.row.col.f32.bf16.bf16.f32 "
        "{%0,%1,%2,%3}, {%4,%5,%6,%7}, {%8,%9}, {%0,%1,%2,%3};"
        : "+f"(c[0]), "+f"(c[1]), "+f"(c[2]), "+f"(c[3])
        : "r"(a[0]), "r"(a[1]), "r"(a[2]), "r"(a[3]), "r"(b0), "r"(b1));
}

// ---------------------------------------------------------------------------
// Split fp32 -> (hi, lo) bf16 pair, elementwise, row-major preserved.
// ---------------------------------------------------------------------------
__global__ __launch_bounds__(256) void split_f32(
    const float* __restrict__ x, __nv_bfloat16* __restrict__ hi,
    __nv_bfloat16* __restrict__ lo)
{
    const int i = (blockIdx.x * 256 + threadIdx.x) * 4;
    float4 v = *(const float4*)(x + i);
    __nv_bfloat16 h0 = __float2bfloat16(v.x);
    __nv_bfloat16 h1 = __float2bfloat16(v.y);
    __nv_bfloat16 h2 = __float2bfloat16(v.z);
    __nv_bfloat16 h3 = __float2bfloat16(v.w);
    __nv_bfloat16 l0 = __float2bfloat16(v.x - __bfloat162float(h0));
    __nv_bfloat16 l1 = __float2bfloat16(v.y - __bfloat162float(h1));
    __nv_bfloat16 l2 = __float2bfloat16(v.z - __bfloat162float(h2));
    __nv_bfloat16 l3 = __float2bfloat16(v.w - __bfloat162float(h3));
    __nv_bfloat162* hp = (__nv_bfloat162*)(hi + i);
    __nv_bfloat162* lp = (__nv_bfloat162*)(lo + i);
    hp[0] = __nv_bfloat162(h0, h1); hp[1] = __nv_bfloat162(h2, h3);
    lp[0] = __nv_bfloat162(l0, l1); lp[1] = __nv_bfloat162(l2, l3);
}

// ---------------------------------------------------------------------------
// Split + transpose: W fp32 [K=1024, N=1024] -> hi/lo bf16 [N, K]
// ---------------------------------------------------------------------------
__global__ __launch_bounds__(256) void split_T(
    const float* __restrict__ W, __nv_bfloat16* __restrict__ hiT,
    __nv_bfloat16* __restrict__ loT)
{
    __shared__ float t[32][33];
    const int tx = threadIdx.x, ty = threadIdx.y;
    const int bn = blockIdx.x * 32, bk = blockIdx.y * 32;
#pragma unroll
    for (int j = 0; j < 4; j++)
        t[ty + j * 8][tx] = W[(size_t)(bk + ty + j * 8) * Dn + bn + tx];
    __syncthreads();
#pragma unroll
    for (int j = 0; j < 4; j++) {
        float v = t[tx][ty + j * 8];
        __nv_bfloat16 h = __float2bfloat16(v);
        __nv_bfloat16 l = __float2bfloat16(v - __bfloat162float(h));
        size_t o = (size_t)(bn + ty + j * 8) * Dn + bk + tx;
        hiT[o] = h;
        loT[o] = l;
    }
}

// ---------------------------------------------------------------------------
// mma.sync bf16-split GEMM: C[8192,1024] = A[8192,1024] * B^T (B stored [N,K])
// A,B as hi/lo bf16 pairs; accumulates hi*hi + hi*lo + lo*hi in fp32.
// 128x128 CTA tile, 8 warps (2M x 4N), 64x32 per warp, BK=32, double buffer.
// SMEM row stride 80B -> ldmatrix conflict-free (16*5 mod 128, 5 coprime 8).
// ---------------------------------------------------------------------------
#define BK        32
#define NSTAGE    (Dn / BK)          // 32
#define ROW_B     80                 // bytes per smem row (32 bf16 + 8 pad)
#define ARR_SZ    (128 * ROW_B)      // 10240 bytes per array tile
#define BUF_SZ    (4 * ARR_SZ)       // Ahi, Alo, Bhi, Blo
#define GEMM_SMEM (2 * BUF_SZ)       // 81920

__global__ __launch_bounds__(256, 1) void gemm_mma(
    const __nv_bfloat16* __restrict__ Ahi, const __nv_bfloat16* __restrict__ Alo,
    const __nv_bfloat16* __restrict__ Bhi, const __nv_bfloat16* __restrict__ Blo,
    float* __restrict__ C)
{
    extern __shared__ char smem[];
    const uint32_t sb = smem_u32(smem);
    const int tid  = threadIdx.x;
    const int wid  = tid >> 5;
    const int lane = tid & 31;
    const int m0 = blockIdx.y * 128;
    const int n0 = blockIdx.x * 128;
    const int m0w = (wid & 1) * 64;        // warp row offset in tile
    const int n0w = (wid >> 1) * 32;       // warp col offset in tile

    const char* src[4] = {(const char*)Ahi, (const char*)Alo,
                          (const char*)Bhi, (const char*)Blo};

    // Per-thread load mapping: 2 chunks of 16B per array per stage
    const int r0c = tid >> 2;           // row 0..63
    const int c16 = tid & 3;            // 16B chunk in 64B row
    // global byte offset (row part) for chunk it (0/1)
    size_t goff[4][2];
#pragma unroll
    for (int arr = 0; arr < 4; arr++) {
        const int tb = (arr < 2) ? m0 : n0;
#pragma unroll
        for (int it = 0; it < 2; it++)
            goff[arr][it] = (size_t)(tb + r0c + it * 64) * 2048 + c16 * 16;
    }
    // smem byte offset (within array tile) for chunk it
    const uint32_t soff0 = r0c * ROW_B + c16 * 16;
    const uint32_t soff1 = (r0c + 64) * ROW_B + c16 * 16;

    float acc[4][4][4];
#pragma unroll
    for (int i = 0; i < 4; i++)
#pragma unroll
        for (int j = 0; j < 4; j++)
#pragma unroll
            for (int k = 0; k < 4; k++) acc[i][j][k] = 0.f;

    // ldmatrix lane addressing
    const int lrow = lane & 15;
    const int lch  = lane >> 4;
    const uint32_t a_lbase = (uint32_t)(m0w + lrow) * ROW_B + lch * 16;
    const uint32_t b_lbase = (uint32_t)(n0w + lrow) * ROW_B + lch * 16;

    // Preload stage 0 directly to smem buffer 0
#pragma unroll
    for (int arr = 0; arr < 4; arr++) {
        char* d = smem + arr * ARR_SZ;
        *(uint4*)(d + soff0) = *(const uint4*)(src[arr] + goff[arr][0]);
        *(uint4*)(d + soff1) = *(const uint4*)(src[arr] + goff[arr][1]);
    }
    __syncthreads();

    for (int kc = 0; kc < NSTAGE; kc++) {
        const int cb = kc & 1;

        // Prefetch next stage into registers
        uint4 pre[4][2];
        if (kc + 1 < NSTAGE) {
            const size_t kb = (size_t)(kc + 1) * 64;
#pragma unroll
            for (int arr = 0; arr < 4; arr++) {
                pre[arr][0] = *(const uint4*)(src[arr] + goff[arr][0] + kb);
                pre[arr][1] = *(const uint4*)(src[arr] + goff[arr][1] + kb);
            }
        }

        // Compute on current buffer: 2 k16-steps x 3 split terms
        const uint32_t bufb = sb + cb * BUF_SZ;
#pragma unroll
        for (int ks = 0; ks < 2; ks++) {
#pragma unroll
            for (int t = 0; t < 3; t++) {
                const int aArr = (t == 2) ? 1 : 0;   // Alo only in term 2
                const int bArr = (t == 1) ? 3 : 2;   // Blo only in term 1
                uint32_t afr[4][4];
#pragma unroll
                for (int mi = 0; mi < 4; mi++)
                    ldm_x4(afr[mi], bufb + aArr * ARR_SZ + a_lbase
                                      + mi * (16 * ROW_B) + ks * 32);
                uint32_t bfr[2][4];
#pragma unroll
                for (int ni = 0; ni < 2; ni++)
                    ldm_x4(bfr[ni], bufb + bArr * ARR_SZ + b_lbase
                                      + ni * (16 * ROW_B) + ks * 32);
                // b-frag for n-tile (ni*2)   = {r0, r2}
                // b-frag for n-tile (ni*2+1) = {r1, r3}
#pragma unroll
                for (int mi = 0; mi < 4; mi++) {
#pragma unroll
                    for (int ni = 0; ni < 2; ni++) {
                        mma_bf16(acc[mi][ni * 2 + 0], afr[mi], bfr[ni][0], bfr[ni][2]);
                        mma_bf16(acc[mi][ni * 2 + 1], afr[mi], bfr[ni][1], bfr[ni][3]);
                    }
                }
            }
        }

        __syncthreads();
        if (kc + 1 < NSTAGE) {
            char* d0 = smem + (cb ^ 1) * BUF_SZ;
#pragma unroll
            for (int arr = 0; arr < 4; arr++) {
                *(uint4*)(d0 + arr * ARR_SZ + soff0) = pre[arr][0];
                *(uint4*)(d0 + arr * ARR_SZ + soff1) = pre[arr][1];
            }
            __syncthreads();
        }
    }

    // Epilogue: c-frag layout m16n8: {c0,c1} row=lane/4 col=(lane%4)*2(+1),
    // {c2,c3} row+8.
    const int erow = lane >> 2;
    const int ecol = (lane & 3) * 2;
#pragma unroll
    for (int mi = 0; mi < 4; mi++) {
#pragma unroll
        for (int nj = 0; nj < 4; nj++) {
            float* Cp = C + (size_t)(m0 + m0w + mi * 16 + erow) * Dn
                          + n0 + n0w + nj * 8 + ecol;
            *(float2*)(Cp)            = make_float2(acc[mi][nj][0], acc[mi][nj][1]);
            *(float2*)(Cp + 8 * Dn)   = make_float2(acc[mi][nj][2], acc[mi][nj][3]);
        }
    }
}

// ---------------------------------------------------------------------------
// Flash attention, fp32 (unchanged from R1).
// ---------------------------------------------------------------------------
#define PAD 68
__global__ __launch_bounds__(256) void flash_attn()
{
    extern __shared__ float sm[];
    float (*Qs)[PAD]  = (float(*)[PAD])(sm);
    float (*KsT)[PAD] = (float(*)[PAD])(sm + 64 * PAD);
    float (*Vs)[PAD]  = (float(*)[PAD])(sm + 2 * 64 * PAD);
    float (*Ps)[PAD]  = (float(*)[PAD])(sm + 3 * 64 * PAD);

    const int tid = threadIdx.x;
    const int qt = blockIdx.x, hh = blockIdx.y, bb = blockIdx.z;
    const int tr = tid >> 4, tc = tid & 15;
    const int tr4 = tr * 4, tc4 = tc * 4;
    const int lr = tid >> 2;
    const int lc = (tid & 3) << 4;
    const float scale = 0.125f;

    {
        const float* qg = g_Q + (bb * Sn + qt * 64 + lr) * Dn + hh * 64 + lc;
#pragma unroll
        for (int m = 0; m < 4; m++) {
            float4 v4 = *(const float4*)(qg + m * 4);
            Qs[lr][lc + m * 4 + 0] = v4.x * scale;
            Qs[lr][lc + m * 4 + 1] = v4.y * scale;
            Qs[lr][lc + m * 4 + 2] = v4.z * scale;
            Qs[lr][lc + m * 4 + 3] = v4.w * scale;
        }
    }

    float m_run[4], l_run[4], o[4][4];
#pragma unroll
    for (int i = 0; i < 4; i++) {
        m_run[i] = -1e30f;
        l_run[i] = 0.f;
#pragma unroll
        for (int j = 0; j < 4; j++) o[i][j] = 0.f;
    }

    for (int kt = 0; kt < Sn / 64; kt++) {
        {
            const float* kg = g_K + (bb * Sn + kt * 64 + lr) * Dn + hh * 64 + lc;
#pragma unroll
            for (int m = 0; m < 4; m++) {
                float4 v4 = *(const float4*)(kg + m * 4);
                KsT[lc + m * 4 + 0][lr] = v4.x;
                KsT[lc + m * 4 + 1][lr] = v4.y;
                KsT[lc + m * 4 + 2][lr] = v4.z;
                KsT[lc + m * 4 + 3][lr] = v4.w;
            }
            const float* vg = g_V + (bb * Sn + kt * 64 + lr) * Dn + hh * 64 + lc;
#pragma unroll
            for (int m = 0; m < 4; m++)
                *(float4*)(&Vs[lr][lc + m * 4]) = *(const float4*)(vg + m * 4);
        }
        __syncthreads();

        float s[4][4];
#pragma unroll
        for (int i = 0; i < 4; i++)
#pragma unroll
            for (int j = 0; j < 4; j++) s[i][j] = 0.f;

#pragma unroll 4
        for (int k4 = 0; k4 < 16; k4++) {
            float qa[4][4];
#pragma unroll
            for (int i = 0; i < 4; i++)
                *(float4*)(qa[i]) = *(const float4*)(&Qs[tr4 + i][k4 * 4]);
#pragma unroll
            for (int m = 0; m < 4; m++) {
                float4 kv = *(const float4*)(&KsT[k4 * 4 + m][tc4]);
#pragma unroll
                for (int i = 0; i < 4; i++) {
                    s[i][0] = fmaf(qa[i][m], kv.x, s[i][0]);
                    s[i][1] = fmaf(qa[i][m], kv.y, s[i][1]);
                    s[i][2] = fmaf(qa[i][m], kv.z, s[i][2]);
                    s[i][3] = fmaf(qa[i][m], kv.w, s[i][3]);
                }
            }
        }

        float alpha[4];
#pragma unroll
        for (int i = 0; i < 4; i++) {
            float mx = fmaxf(fmaxf(s[i][0], s[i][1]), fmaxf(s[i][2], s[i][3]));
#pragma unroll
            for (int off = 8; off > 0; off >>= 1)
                mx = fmaxf(mx, __shfl_xor_sync(0xffffffffu, mx, off));
            float mnew = fmaxf(m_run[i], mx);
            alpha[i] = __expf(m_run[i] - mnew);
            m_run[i] = mnew;
            float ls = 0.f;
#pragma unroll
            for (int j = 0; j < 4; j++) {
                s[i][j] = __expf(s[i][j] - mnew);
                ls += s[i][j];
            }
#pragma unroll
            for (int off = 8; off > 0; off >>= 1)
                ls += __shfl_xor_sync(0xffffffffu, ls, off);
            l_run[i] = l_run[i] * alpha[i] + ls;
            *(float4*)(&Ps[tr4 + i][tc4]) = make_float4(s[i][0], s[i][1], s[i][2], s[i][3]);
        }
        __syncwarp(0xffffffffu);

#pragma unroll
        for (int i = 0; i < 4; i++)
#pragma unroll
            for (int j = 0; j < 4; j++) o[i][j] *= alpha[i];

#pragma unroll 4
        for (int k4 = 0; k4 < 16; k4++) {
            float pa[4][4];
#pragma unroll
            for (int i = 0; i < 4; i++)
                *(float4*)(pa[i]) = *(const float4*)(&Ps[tr4 + i][k4 * 4]);
#pragma unroll
            for (int m = 0; m < 4; m++) {
                float4 vv = *(const float4*)(&Vs[k4 * 4 + m][tc4]);
#pragma unroll
                for (int i = 0; i < 4; i++) {
                    o[i][0] = fmaf(pa[i][m], vv.x, o[i][0]);
                    o[i][1] = fmaf(pa[i][m], vv.y, o[i][1]);
                    o[i][2] = fmaf(pa[i][m], vv.z, o[i][2]);
                    o[i][3] = fmaf(pa[i][m], vv.w, o[i][3]);
                }
            }
        }
        __syncthreads();
    }

#pragma unroll
    for (int i = 0; i < 4; i++) {
        float inv = 1.0f / l_run[i];
        float4 r = make_float4(o[i][0] * inv, o[i][1] * inv, o[i][2] * inv, o[i][3] * inv);
        *(float4*)(g_AV + (bb * Sn + qt * 64 + tr4 + i) * Dn + hh * 64 + tc4) = r;
    }
}

// ---------------------------------------------------------------------------
// Residual + LayerNorm (unchanged)
// ---------------------------------------------------------------------------
__global__ __launch_bounds__(256) void ln_residual(
    const float* __restrict__ h, const float* __restrict__ gamma,
    const float* __restrict__ beta, float* __restrict__ out)
{
    const int row = blockIdx.x;
    const int tid = threadIdx.x;

    const float4 hv = *(const float4*)(h + row * Dn + tid * 4);
    const float4 av = *(const float4*)(g_AO + row * Dn + tid * 4);
    float4 x = make_float4(hv.x + av.x, hv.y + av.y, hv.z + av.z, hv.w + av.w);

    float s  = x.x + x.y + x.z + x.w;
    float ss = x.x * x.x + x.y * x.y + x.z * x.z + x.w * x.w;
#pragma unroll
    for (int off = 16; off > 0; off >>= 1) {
        s  += __shfl_xor_sync(0xffffffffu, s, off);
        ss += __shfl_xor_sync(0xffffffffu, ss, off);
    }
    __shared__ float rs[8], rss[8];
    if ((tid & 31) == 0) { rs[tid >> 5] = s; rss[tid >> 5] = ss; }
    __syncthreads();
    s = 0.f; ss = 0.f;
#pragma unroll
    for (int w = 0; w < 8; w++) { s += rs[w]; ss += rss[w]; }

    const float mu  = s * (1.0f / Dn);
    const float var = ss * (1.0f / Dn) - mu * mu;
    const float inv = rsqrtf(var + 1e-5f);

    const float4 g4 = *(const float4*)(gamma + tid * 4);
    const float4 b4 = *(const float4*)(beta + tid * 4);
    float4 r;
    r.x = g4.x * (x.x - mu) * inv + b4.x;
    r.y = g4.y * (x.y - mu) * inv + b4.y;
    r.z = g4.z * (x.z - mu) * inv + b4.z;
    r.w = g4.w * (x.w - mu) * inv + b4.w;
    *(float4*)(out + row * Dn + tid * 4) = r;
}

// ---------------------------------------------------------------------------
extern "C" void kernel_launch(void* const* d_in, const int* in_sizes, int n_in,
                              void* d_out, int out_size)
{
    (void)in_sizes; (void)n_in; (void)out_size;
    const float* h     = (const float*)d_in[0];
    const float* Wq    = (const float*)d_in[1];
    const float* Wk    = (const float*)d_in[2];
    const float* Wv    = (const float*)d_in[3];
    const float* Wo    = (const float*)d_in[4];
    const float* gamma = (const float*)d_in[5];
    const float* beta  = (const float*)d_in[6];
    float* out = (float*)d_out;

    float *Qp, *Kp, *Vp, *AVp, *AOp;
    __nv_bfloat16 *hAhi, *hAlo, *AVhi, *AVlo, *Whi, *Wlo;
    cudaGetSymbolAddress((void**)&Qp,   g_Q);
    cudaGetSymbolAddress((void**)&Kp,   g_K);
    cudaGetSymbolAddress((void**)&Vp,   g_V);
    cudaGetSymbolAddress((void**)&AVp,  g_AV);
    cudaGetSymbolAddress((void**)&AOp,  g_AO);
    cudaGetSymbolAddress((void**)&hAhi, g_hA_hi);
    cudaGetSymbolAddress((void**)&hAlo, g_hA_lo);
    cudaGetSymbolAddress((void**)&AVhi, g_AV_hi);
    cudaGetSymbolAddress((void**)&AVlo, g_AV_lo);
    cudaGetSymbolAddress((void**)&Whi,  g_W_hi);
    cudaGetSymbolAddress((void**)&Wlo,  g_W_lo);

    const int flash_smem = 4 * 64 * PAD * (int)sizeof(float);
    cudaFuncSetAttribute(flash_attn, cudaFuncAttributeMaxDynamicSharedMemorySize,
                         flash_smem);
    cudaFuncSetAttribute(gemm_mma, cudaFuncAttributeMaxDynamicSharedMemorySize,
                         GEMM_SMEM);

    // Split inputs into bf16 hi/lo
    split_f32<<<Mn * Dn / 1024, 256>>>(h, hAhi, hAlo);
    dim3 tgrid(32, 32), tblk(32, 8);
    split_T<<<tgrid, tblk>>>(Wq, Whi + 0 * Dn * Dn, Wlo + 0 * Dn * Dn);
    split_T<<<tgrid, tblk>>>(Wk, Whi + 1 * Dn * Dn, Wlo + 1 * Dn * Dn);
    split_T<<<tgrid, tblk>>>(Wv, Whi + 2 * Dn * Dn, Wlo + 2 * Dn * Dn);
    split_T<<<tgrid, tblk>>>(Wo, Whi + 3 * Dn * Dn, Wlo + 3 * Dn * Dn);

    // QKV projections on tensor cores (mma.sync)
    dim3 ggrid(Dn / 128, Mn / 128);   // (8, 64)
    gemm_mma<<<ggrid, 256, GEMM_SMEM>>>(hAhi, hAlo, Whi + 0 * Dn * Dn, Wlo + 0 * Dn * Dn, Qp);
    gemm_mma<<<ggrid, 256, GEMM_SMEM>>>(hAhi, hAlo, Whi + 1 * Dn * Dn, Wlo + 1 * Dn * Dn, Kp);
    gemm_mma<<<ggrid, 256, GEMM_SMEM>>>(hAhi, hAlo, Whi + 2 * Dn * Dn, Wlo + 2 * Dn * Dn, Vp);

    flash_attn<<<dim3(Sn / 64, Hn, Bn), 256, flash_smem>>>();

    // Output projection
    split_f32<<<Mn * Dn / 1024, 256>>>(AVp, AVhi, AVlo);
    gemm_mma<<<ggrid, 256, GEMM_SMEM>>>(AVhi, AVlo, Whi + 3 * Dn * Dn, Wlo + 3 * Dn * Dn, AOp);

    ln_residual<<<Mn, 256>>>(h, gamma, beta, out);
}

// round 5
// speedup vs baseline: 2.4684x; 1.8376x over previous
#include <cuda_runtime.h>
#include <cuda_bf16.h>
#include <cstdint>
#include <math.h>

#define Bn 4
#define Sn 2048
#define Dn 1024
#define Hn 16
#define DHn 64
#define Mn (Bn * Sn)   // 8192

// ---------------------------------------------------------------------------
// Device scratch
// ---------------------------------------------------------------------------
__device__ float g_AO[Mn * Dn];

__device__ __nv_bfloat16 g_hA_hi[Mn * Dn];
__device__ __nv_bfloat16 g_hA_lo[Mn * Dn];
__device__ __nv_bfloat16 g_W_hi[4 * Dn * Dn];   // transposed [N,K], order q,k,v,o
__device__ __nv_bfloat16 g_W_lo[4 * Dn * Dn];

__device__ __nv_bfloat16 g_Qh[Mn * Dn];  // pre-scaled by 0.125
__device__ __nv_bfloat16 g_Ql[Mn * Dn];
__device__ __nv_bfloat16 g_Kh[Mn * Dn];
__device__ __nv_bfloat16 g_Kl[Mn * Dn];
__device__ __nv_bfloat16 g_Vh[Mn * Dn];
__device__ __nv_bfloat16 g_Vl[Mn * Dn];
__device__ __nv_bfloat16 g_AVh[Mn * Dn];
__device__ __nv_bfloat16 g_AVl[Mn * Dn];

// ---------------------------------------------------------------------------
__device__ __forceinline__ uint32_t smem_u32(const void* p) {
    uint32_t a;
    asm("{ .reg .u64 t; cvta.to.shared.u64 t, %1; cvt.u32.u64 %0, t; }"
        : "=r"(a) : "l"(p));
    return a;
}

__device__ __forceinline__ void ldm_x4(uint32_t* r, uint32_t addr) {
    asm volatile("ldmatrix.sync.aligned.m8n8.x4.shared.b16 {%0,%1,%2,%3}, [%4];"
                 : "=r"(r[0]), "=r"(r[1]), "=r"(r[2]), "=r"(r[3]) : "r"(addr));
}
__device__ __forceinline__ void ldm_x4t(uint32_t* r, uint32_t addr) {
    asm volatile("ldmatrix.sync.aligned.m8n8.x4.trans.shared.b16 {%0,%1,%2,%3}, [%4];"
                 : "=r"(r[0]), "=r"(r[1]), "=r"(r[2]), "=r"(r[3]) : "r"(addr));
}

__device__ __forceinline__ void mma_bf16(float* c, const uint32_t* a,
                                         uint32_t b0, uint32_t b1) {
    asm volatile(
        "mma.sync.aligned.m16n8k16.row.col.f32.bf16.bf16.f32 "
        "{%0,%1,%2,%3}, {%4,%5,%6,%7}, {%8,%9}, {%0,%1,%2,%3};"
        : "+f"(c[0]), "+f"(c[1]), "+f"(c[2]), "+f"(c[3])
        : "r"(a[0]), "r"(a[1]), "r"(a[2]), "r"(a[3]), "r"(b0), "r"(b1));
}

// pack two floats into bf16x2: first arg -> low half, second -> high half
__device__ __forceinline__ uint32_t pack_bf16x2(float lo, float hi) {
    uint32_t d;
    asm("cvt.rn.bf16x2.f32 %0, %1, %2;" : "=r"(d) : "f"(hi), "f"(lo));
    return d;
}

// ---------------------------------------------------------------------------
// Split fp32 -> (hi, lo) bf16 pair, elementwise, row-major preserved.
// ---------------------------------------------------------------------------
__global__ __launch_bounds__(256) void split_f32(
    const float* __restrict__ x, __nv_bfloat16* __restrict__ hi,
    __nv_bfloat16* __restrict__ lo)
{
    const int i = (blockIdx.x * 256 + threadIdx.x) * 4;
    float4 v = *(const float4*)(x + i);
    __nv_bfloat16 h0 = __float2bfloat16(v.x);
    __nv_bfloat16 h1 = __float2bfloat16(v.y);
    __nv_bfloat16 h2 = __float2bfloat16(v.z);
    __nv_bfloat16 h3 = __float2bfloat16(v.w);
    __nv_bfloat16 l0 = __float2bfloat16(v.x - __bfloat162float(h0));
    __nv_bfloat16 l1 = __float2bfloat16(v.y - __bfloat162float(h1));
    __nv_bfloat16 l2 = __float2bfloat16(v.z - __bfloat162float(h2));
    __nv_bfloat16 l3 = __float2bfloat16(v.w - __bfloat162float(h3));
    __nv_bfloat162* hp = (__nv_bfloat162*)(hi + i);
    __nv_bfloat162* lp = (__nv_bfloat162*)(lo + i);
    hp[0] = __nv_bfloat162(h0, h1); hp[1] = __nv_bfloat162(h2, h3);
    lp[0] = __nv_bfloat162(l0, l1); lp[1] = __nv_bfloat162(l2, l3);
}

// ---------------------------------------------------------------------------
// Split + transpose: W fp32 [K=1024, N=1024] -> hi/lo bf16 [N, K]
// ---------------------------------------------------------------------------
__global__ __launch_bounds__(256) void split_T(
    const float* __restrict__ W, __nv_bfloat16* __restrict__ hiT,
    __nv_bfloat16* __restrict__ loT)
{
    __shared__ float t[32][33];
    const int tx = threadIdx.x, ty = threadIdx.y;
    const int bn = blockIdx.x * 32, bk = blockIdx.y * 32;
#pragma unroll
    for (int j = 0; j < 4; j++)
        t[ty + j * 8][tx] = W[(size_t)(bk + ty + j * 8) * Dn + bn + tx];
    __syncthreads();
#pragma unroll
    for (int j = 0; j < 4; j++) {
        float v = t[tx][ty + j * 8];
        __nv_bfloat16 h = __float2bfloat16(v);
        __nv_bfloat16 l = __float2bfloat16(v - __bfloat162float(h));
        size_t o = (size_t)(bn + ty + j * 8) * Dn + bk + tx;
        hiT[o] = h;
        loT[o] = l;
    }
}

// ---------------------------------------------------------------------------
// GEMM mainloop (mma.sync bf16-split), template-dispatched epilogue.
// EPI = 0: fp32 output C.  EPI = 1: hi/lo bf16 split output (scaled).
// 128x128 CTA tile, 8 warps (2M x 4N), 64x32 per warp, BK=32, double buffer.
// ---------------------------------------------------------------------------
#define BK        32
#define NSTAGE    (Dn / BK)          // 32
#define ROW_B     80                 // bytes per smem row (32 bf16 + 8 pad)
#define ARR_SZ    (128 * ROW_B)      // 10240 bytes per array tile
#define BUF_SZ    (4 * ARR_SZ)
#define GEMM_SMEM (2 * BUF_SZ)       // 81920

template <int EPI>
__device__ __forceinline__ void gemm_body(
    const __nv_bfloat16* __restrict__ Ahi, const __nv_bfloat16* __restrict__ Alo,
    const __nv_bfloat16* __restrict__ Bhi, const __nv_bfloat16* __restrict__ Blo,
    float* __restrict__ C,
    __nv_bfloat16* __restrict__ Chi, __nv_bfloat16* __restrict__ Clo, float scale)
{
    extern __shared__ char smem[];
    const uint32_t sb = smem_u32(smem);
    const int tid  = threadIdx.x;
    const int wid  = tid >> 5;
    const int lane = tid & 31;
    const int m0 = blockIdx.y * 128;
    const int n0 = blockIdx.x * 128;
    const int m0w = (wid & 1) * 64;
    const int n0w = (wid >> 1) * 32;

    const char* src[4] = {(const char*)Ahi, (const char*)Alo,
                          (const char*)Bhi, (const char*)Blo};

    const int r0c = tid >> 2;
    const int c16 = tid & 3;
    size_t goff[4][2];
#pragma unroll
    for (int arr = 0; arr < 4; arr++) {
        const int tb = (arr < 2) ? m0 : n0;
#pragma unroll
        for (int it = 0; it < 2; it++)
            goff[arr][it] = (size_t)(tb + r0c + it * 64) * 2048 + c16 * 16;
    }
    const uint32_t soff0 = r0c * ROW_B + c16 * 16;
    const uint32_t soff1 = (r0c + 64) * ROW_B + c16 * 16;

    float acc[4][4][4];
#pragma unroll
    for (int i = 0; i < 4; i++)
#pragma unroll
        for (int j = 0; j < 4; j++)
#pragma unroll
            for (int k = 0; k < 4; k++) acc[i][j][k] = 0.f;

    const int lrow = lane & 15;
    const int lch  = lane >> 4;
    const uint32_t a_lbase = (uint32_t)(m0w + lrow) * ROW_B + lch * 16;
    const uint32_t b_lbase = (uint32_t)(n0w + lrow) * ROW_B + lch * 16;

#pragma unroll
    for (int arr = 0; arr < 4; arr++) {
        char* d = smem + arr * ARR_SZ;
        *(uint4*)(d + soff0) = *(const uint4*)(src[arr] + goff[arr][0]);
        *(uint4*)(d + soff1) = *(const uint4*)(src[arr] + goff[arr][1]);
    }
    __syncthreads();

    for (int kc = 0; kc < NSTAGE; kc++) {
        const int cb = kc & 1;
        uint4 pre[4][2];
        if (kc + 1 < NSTAGE) {
            const size_t kb = (size_t)(kc + 1) * 64;
#pragma unroll
            for (int arr = 0; arr < 4; arr++) {
                pre[arr][0] = *(const uint4*)(src[arr] + goff[arr][0] + kb);
                pre[arr][1] = *(const uint4*)(src[arr] + goff[arr][1] + kb);
            }
        }

        const uint32_t bufb = sb + cb * BUF_SZ;
#pragma unroll
        for (int ks = 0; ks < 2; ks++) {
#pragma unroll
            for (int t = 0; t < 3; t++) {
                const int aArr = (t == 2) ? 1 : 0;
                const int bArr = (t == 1) ? 3 : 2;
                uint32_t afr[4][4];
#pragma unroll
                for (int mi = 0; mi < 4; mi++)
                    ldm_x4(afr[mi], bufb + aArr * ARR_SZ + a_lbase
                                      + mi * (16 * ROW_B) + ks * 32);
                uint32_t bfr[2][4];
#pragma unroll
                for (int ni = 0; ni < 2; ni++)
                    ldm_x4(bfr[ni], bufb + bArr * ARR_SZ + b_lbase
                                      + ni * (16 * ROW_B) + ks * 32);
#pragma unroll
                for (int mi = 0; mi < 4; mi++) {
#pragma unroll
                    for (int ni = 0; ni < 2; ni++) {
                        mma_bf16(acc[mi][ni * 2 + 0], afr[mi], bfr[ni][0], bfr[ni][2]);
                        mma_bf16(acc[mi][ni * 2 + 1], afr[mi], bfr[ni][1], bfr[ni][3]);
                    }
                }
            }
        }

        __syncthreads();
        if (kc + 1 < NSTAGE) {
            char* d0 = smem + (cb ^ 1) * BUF_SZ;
#pragma unroll
            for (int arr = 0; arr < 4; arr++) {
                *(uint4*)(d0 + arr * ARR_SZ + soff0) = pre[arr][0];
                *(uint4*)(d0 + arr * ARR_SZ + soff1) = pre[arr][1];
            }
            __syncthreads();
        }
    }

    // Epilogue
    const int erow = lane >> 2;
    const int ecol = (lane & 3) * 2;
#pragma unroll
    for (int mi = 0; mi < 4; mi++) {
#pragma unroll
        for (int nj = 0; nj < 4; nj++) {
            size_t base0 = (size_t)(m0 + m0w + mi * 16 + erow) * Dn
                         + n0 + n0w + nj * 8 + ecol;
            if (EPI == 0) {
                *(float2*)(C + base0)          = make_float2(acc[mi][nj][0], acc[mi][nj][1]);
                *(float2*)(C + base0 + 8 * Dn) = make_float2(acc[mi][nj][2], acc[mi][nj][3]);
            } else {
#pragma unroll
                for (int half = 0; half < 2; half++) {
                    size_t b = base0 + half * 8 * Dn;
                    float v0 = acc[mi][nj][half * 2 + 0] * scale;
                    float v1 = acc[mi][nj][half * 2 + 1] * scale;
                    __nv_bfloat16 h0 = __float2bfloat16(v0);
                    __nv_bfloat16 h1 = __float2bfloat16(v1);
                    __nv_bfloat16 l0 = __float2bfloat16(v0 - __bfloat162float(h0));
                    __nv_bfloat16 l1 = __float2bfloat16(v1 - __bfloat162float(h1));
                    *(__nv_bfloat162*)(Chi + b) = __nv_bfloat162(h0, h1);
                    *(__nv_bfloat162*)(Clo + b) = __nv_bfloat162(l0, l1);
                }
            }
        }
    }
}

__global__ __launch_bounds__(256, 1) void gemm_mma(
    const __nv_bfloat16* __restrict__ Ahi, const __nv_bfloat16* __restrict__ Alo,
    const __nv_bfloat16* __restrict__ Bhi, const __nv_bfloat16* __restrict__ Blo,
    float* __restrict__ C)
{
    gemm_body<0>(Ahi, Alo, Bhi, Blo, C, nullptr, nullptr, 1.0f);
}

__global__ __launch_bounds__(256, 1) void gemm_mma_split(
    const __nv_bfloat16* __restrict__ Ahi, const __nv_bfloat16* __restrict__ Alo,
    const __nv_bfloat16* __restrict__ Bhi, const __nv_bfloat16* __restrict__ Blo,
    __nv_bfloat16* __restrict__ Chi, __nv_bfloat16* __restrict__ Clo, float scale)
{
    gemm_body<1>(Ahi, Alo, Bhi, Blo, nullptr, Chi, Clo, scale);
}

// ---------------------------------------------------------------------------
// Flash attention on mma.sync bf16 with hi/lo splits.
// Grid (32, 16, 4): 64 q-rows per CTA, 128 threads (4 warps x m16).
// SMEM: Qh,Ql,Kh,Kl,Vh,Vl tiles 64x64 bf16, row stride 144B.
// ---------------------------------------------------------------------------
#define FROW 144
#define FARR (64 * FROW)          // 9216
#define FLASH_SMEM (6 * FARR)     // 55296

__global__ __launch_bounds__(128) void flash_mma()
{
    extern __shared__ char sm[];
    const uint32_t sb = smem_u32(sm);
    const int tid = threadIdx.x;
    const int lane = tid & 31;
    const int w = tid >> 5;
    const int qt = blockIdx.x, hh = blockIdx.y, bb = blockIdx.z;

    const size_t headoff = (size_t)hh * 64;

    // Load Q hi/lo tiles (64 x 64 bf16 each)
#pragma unroll
    for (int i = 0; i < 4; i++) {
        const int idx = tid + 128 * i;
        const int r = idx >> 3, ch = idx & 7;
        const size_t g = (size_t)(bb * Sn + qt * 64 + r) * Dn + headoff + ch * 8;
        const uint32_t so = r * FROW + ch * 16;
        *(uint4*)(sm + 0 * FARR + so) = *(const uint4*)(g_Qh + g);
        *(uint4*)(sm + 1 * FARR + so) = *(const uint4*)(g_Ql + g);
    }

    const int lrow = lane & 15;
    const int lch  = lane >> 4;
    const uint32_t aoff = (uint32_t)(w * 16 + lrow) * FROW + lch * 16;     // Q (A)
    uint32_t boff[4];
#pragma unroll
    for (int np = 0; np < 4; np++)
        boff[np] = (uint32_t)(np * 16 + lrow) * FROW + lch * 16;           // K (B)

    float o[8][4];
#pragma unroll
    for (int j = 0; j < 8; j++)
#pragma unroll
        for (int k = 0; k < 4; k++) o[j][k] = 0.f;
    float m0r = -1e30f, m1r = -1e30f, l0r = 0.f, l1r = 0.f;

    for (int kt = 0; kt < Sn / 64; kt++) {
        __syncthreads();
#pragma unroll
        for (int i = 0; i < 4; i++) {
            const int idx = tid + 128 * i;
            const int r = idx >> 3, ch = idx & 7;
            const size_t g = (size_t)(bb * Sn + kt * 64 + r) * Dn + headoff + ch * 8;
            const uint32_t so = r * FROW + ch * 16;
            *(uint4*)(sm + 2 * FARR + so) = *(const uint4*)(g_Kh + g);
            *(uint4*)(sm + 3 * FARR + so) = *(const uint4*)(g_Kl + g);
            *(uint4*)(sm + 4 * FARR + so) = *(const uint4*)(g_Vh + g);
            *(uint4*)(sm + 5 * FARR + so) = *(const uint4*)(g_Vl + g);
        }
        __syncthreads();

        // ---- S = Q*K^T (3 split terms), n=64 keys ----
        float s[8][4];
#pragma unroll
        for (int j = 0; j < 8; j++)
#pragma unroll
            for (int k = 0; k < 4; k++) s[j][k] = 0.f;

#pragma unroll
        for (int ks = 0; ks < 4; ks++) {
            uint32_t qh[4], ql[4];
            ldm_x4(qh, sb + 0 * FARR + aoff + ks * 32);
            ldm_x4(ql, sb + 1 * FARR + aoff + ks * 32);
#pragma unroll
            for (int np = 0; np < 4; np++) {
                uint32_t kh[4], kl[4];
                ldm_x4(kh, sb + 2 * FARR + boff[np] + ks * 32);
                ldm_x4(kl, sb + 3 * FARR + boff[np] + ks * 32);
                mma_bf16(s[2 * np + 0], qh, kh[0], kh[2]);
                mma_bf16(s[2 * np + 1], qh, kh[1], kh[3]);
                mma_bf16(s[2 * np + 0], qh, kl[0], kl[2]);
                mma_bf16(s[2 * np + 1], qh, kl[1], kl[3]);
                mma_bf16(s[2 * np + 0], ql, kh[0], kh[2]);
                mma_bf16(s[2 * np + 1], ql, kh[1], kh[3]);
            }
        }

        // ---- Online softmax (rows lane/4 and lane/4+8) ----
        float mx0 = -1e30f, mx1 = -1e30f;
#pragma unroll
        for (int j = 0; j < 8; j++) {
            mx0 = fmaxf(mx0, fmaxf(s[j][0], s[j][1]));
            mx1 = fmaxf(mx1, fmaxf(s[j][2], s[j][3]));
        }
        mx0 = fmaxf(mx0, __shfl_xor_sync(0xffffffffu, mx0, 1));
        mx0 = fmaxf(mx0, __shfl_xor_sync(0xffffffffu, mx0, 2));
        mx1 = fmaxf(mx1, __shfl_xor_sync(0xffffffffu, mx1, 1));
        mx1 = fmaxf(mx1, __shfl_xor_sync(0xffffffffu, mx1, 2));

        const float mn0 = fmaxf(m0r, mx0);
        const float mn1 = fmaxf(m1r, mx1);
        const float a0 = __expf(m0r - mn0);
        const float a1 = __expf(m1r - mn1);
        m0r = mn0; m1r = mn1;

        uint32_t phi[8][2], plo[8][2];
        float sum0 = 0.f, sum1 = 0.f;
#pragma unroll
        for (int j = 0; j < 8; j++) {
            float p00 = __expf(s[j][0] - mn0);
            float p01 = __expf(s[j][1] - mn0);
            float p10 = __expf(s[j][2] - mn1);
            float p11 = __expf(s[j][3] - mn1);
            sum0 += p00 + p01;
            sum1 += p10 + p11;
            __nv_bfloat16 h00 = __float2bfloat16(p00);
            __nv_bfloat16 h01 = __float2bfloat16(p01);
            __nv_bfloat16 h10 = __float2bfloat16(p10);
            __nv_bfloat16 h11 = __float2bfloat16(p11);
            phi[j][0] = ((uint32_t)__bfloat16_as_ushort(h01) << 16)
                      |  (uint32_t)__bfloat16_as_ushort(h00);
            phi[j][1] = ((uint32_t)__bfloat16_as_ushort(h11) << 16)
                      |  (uint32_t)__bfloat16_as_ushort(h10);
            plo[j][0] = pack_bf16x2(p00 - __bfloat162float(h00),
                                    p01 - __bfloat162float(h01));
            plo[j][1] = pack_bf16x2(p10 - __bfloat162float(h10),
                                    p11 - __bfloat162float(h11));
        }
        sum0 += __shfl_xor_sync(0xffffffffu, sum0, 1);
        sum0 += __shfl_xor_sync(0xffffffffu, sum0, 2);
        sum1 += __shfl_xor_sync(0xffffffffu, sum1, 1);
        sum1 += __shfl_xor_sync(0xffffffffu, sum1, 2);
        l0r = l0r * a0 + sum0;
        l1r = l1r * a1 + sum1;

#pragma unroll
        for (int j = 0; j < 8; j++) {
            o[j][0] *= a0; o[j][1] *= a0;
            o[j][2] *= a1; o[j][3] *= a1;
        }

        // ---- O += P * V (3 split terms), V via ldmatrix.trans ----
#pragma unroll
        for (int ks = 0; ks < 4; ks++) {
            uint32_t ah[4] = {phi[2 * ks][0], phi[2 * ks][1],
                              phi[2 * ks + 1][0], phi[2 * ks + 1][1]};
            uint32_t al[4] = {plo[2 * ks][0], plo[2 * ks][1],
                              plo[2 * ks + 1][0], plo[2 * ks + 1][1]};
            const uint32_t vbase = (uint32_t)(ks * 16 + lrow) * FROW + lch * 16;
#pragma unroll
            for (int np = 0; np < 4; np++) {
                uint32_t vh[4], vl[4];
                ldm_x4t(vh, sb + 4 * FARR + vbase + np * 32);
                ldm_x4t(vl, sb + 5 * FARR + vbase + np * 32);
                mma_bf16(o[2 * np + 0], ah, vh[0], vh[1]);
                mma_bf16(o[2 * np + 1], ah, vh[2], vh[3]);
                mma_bf16(o[2 * np + 0], al, vh[0], vh[1]);
                mma_bf16(o[2 * np + 1], al, vh[2], vh[3]);
                mma_bf16(o[2 * np + 0], ah, vl[0], vl[1]);
                mma_bf16(o[2 * np + 1], ah, vl[2], vl[3]);
            }
        }
    }

    // Epilogue: normalize, split to hi/lo bf16, write AV
    const float inv0 = 1.0f / l0r;
    const float inv1 = 1.0f / l1r;
    const size_t row0 = (size_t)(bb * Sn + qt * 64 + w * 16 + (lane >> 2));
    const size_t row1 = row0 + 8;
    const size_t colb = headoff + (lane & 3) * 2;
#pragma unroll
    for (int j = 0; j < 8; j++) {
        float v0 = o[j][0] * inv0, v1 = o[j][1] * inv0;
        float v2 = o[j][2] * inv1, v3 = o[j][3] * inv1;
        __nv_bfloat16 h0 = __float2bfloat16(v0);
        __nv_bfloat16 h1 = __float2bfloat16(v1);
        __nv_bfloat16 h2 = __float2bfloat16(v2);
        __nv_bfloat16 h3 = __float2bfloat16(v3);
        size_t b0 = row0 * Dn + colb + j * 8;
        size_t b1 = row1 * Dn + colb + j * 8;
        *(__nv_bfloat162*)(g_AVh + b0) = __nv_bfloat162(h0, h1);
        *(__nv_bfloat162*)(g_AVh + b1) = __nv_bfloat162(h2, h3);
        *(__nv_bfloat162*)(g_AVl + b0) =
            __nv_bfloat162(__float2bfloat16(v0 - __bfloat162float(h0)),
                           __float2bfloat16(v1 - __bfloat162float(h1)));
        *(__nv_bfloat162*)(g_AVl + b1) =
            __nv_bfloat162(__float2bfloat16(v2 - __bfloat162float(h2)),
                           __float2bfloat16(v3 - __bfloat162float(h3)));
    }
}

// ---------------------------------------------------------------------------
// Residual + LayerNorm
// ---------------------------------------------------------------------------
__global__ __launch_bounds__(256) void ln_residual(
    const float* __restrict__ h, const float* __restrict__ gamma,
    const float* __restrict__ beta, float* __restrict__ out)
{
    const int row = blockIdx.x;
    const int tid = threadIdx.x;

    const float4 hv = *(const float4*)(h + row * Dn + tid * 4);
    const float4 av = *(const float4*)(g_AO + row * Dn + tid * 4);
    float4 x = make_float4(hv.x + av.x, hv.y + av.y, hv.z + av.z, hv.w + av.w);

    float s  = x.x + x.y + x.z + x.w;
    float ss = x.x * x.x + x.y * x.y + x.z * x.z + x.w * x.w;
#pragma unroll
    for (int off = 16; off > 0; off >>= 1) {
        s  += __shfl_xor_sync(0xffffffffu, s, off);
        ss += __shfl_xor_sync(0xffffffffu, ss, off);
    }
    __shared__ float rs[8], rss[8];
    if ((tid & 31) == 0) { rs[tid >> 5] = s; rss[tid >> 5] = ss; }
    __syncthreads();
    s = 0.f; ss = 0.f;
#pragma unroll
    for (int w = 0; w < 8; w++) { s += rs[w]; ss += rss[w]; }

    const float mu  = s * (1.0f / Dn);
    const float var = ss * (1.0f / Dn) - mu * mu;
    const float inv = rsqrtf(var + 1e-5f);

    const float4 g4 = *(const float4*)(gamma + tid * 4);
    const float4 b4 = *(const float4*)(beta + tid * 4);
    float4 r;
    r.x = g4.x * (x.x - mu) * inv + b4.x;
    r.y = g4.y * (x.y - mu) * inv + b4.y;
    r.z = g4.z * (x.z - mu) * inv + b4.z;
    r.w = g4.w * (x.w - mu) * inv + b4.w;
    *(float4*)(out + row * Dn + tid * 4) = r;
}

// ---------------------------------------------------------------------------
extern "C" void kernel_launch(void* const* d_in, const int* in_sizes, int n_in,
                              void* d_out, int out_size)
{
    (void)in_sizes; (void)n_in; (void)out_size;
    const float* h     = (const float*)d_in[0];
    const float* Wq    = (const float*)d_in[1];
    const float* Wk    = (const float*)d_in[2];
    const float* Wv    = (const float*)d_in[3];
    const float* Wo    = (const float*)d_in[4];
    const float* gamma = (const float*)d_in[5];
    const float* beta  = (const float*)d_in[6];
    float* out = (float*)d_out;

    float* AOp;
    __nv_bfloat16 *hAhi, *hAlo, *Whi, *Wlo;
    __nv_bfloat16 *Qh, *Ql, *Kh, *Kl, *Vh, *Vl, *AVh, *AVl;
    cudaGetSymbolAddress((void**)&AOp,  g_AO);
    cudaGetSymbolAddress((void**)&hAhi, g_hA_hi);
    cudaGetSymbolAddress((void**)&hAlo, g_hA_lo);
    cudaGetSymbolAddress((void**)&Whi,  g_W_hi);
    cudaGetSymbolAddress((void**)&Wlo,  g_W_lo);
    cudaGetSymbolAddress((void**)&Qh,   g_Qh);
    cudaGetSymbolAddress((void**)&Ql,   g_Ql);
    cudaGetSymbolAddress((void**)&Kh,   g_Kh);
    cudaGetSymbolAddress((void**)&Kl,   g_Kl);
    cudaGetSymbolAddress((void**)&Vh,   g_Vh);
    cudaGetSymbolAddress((void**)&Vl,   g_Vl);
    cudaGetSymbolAddress((void**)&AVh,  g_AVh);
    cudaGetSymbolAddress((void**)&AVl,  g_AVl);

    cudaFuncSetAttribute(gemm_mma, cudaFuncAttributeMaxDynamicSharedMemorySize,
                         GEMM_SMEM);
    cudaFuncSetAttribute(gemm_mma_split, cudaFuncAttributeMaxDynamicSharedMemorySize,
                         GEMM_SMEM);
    cudaFuncSetAttribute(flash_mma, cudaFuncAttributeMaxDynamicSharedMemorySize,
                         FLASH_SMEM);

    // Split h and weights into bf16 hi/lo
    split_f32<<<Mn * Dn / 1024, 256>>>(h, hAhi, hAlo);
    dim3 tgrid(32, 32), tblk(32, 8);
    split_T<<<tgrid, tblk>>>(Wq, Whi + 0 * (size_t)Dn * Dn, Wlo + 0 * (size_t)Dn * Dn);
    split_T<<<tgrid, tblk>>>(Wk, Whi + 1 * (size_t)Dn * Dn, Wlo + 1 * (size_t)Dn * Dn);
    split_T<<<tgrid, tblk>>>(Wv, Whi + 2 * (size_t)Dn * Dn, Wlo + 2 * (size_t)Dn * Dn);
    split_T<<<tgrid, tblk>>>(Wo, Whi + 3 * (size_t)Dn * Dn, Wlo + 3 * (size_t)Dn * Dn);

    // Q/K/V projections -> hi/lo bf16 (Q pre-scaled by 1/8)
    dim3 ggrid(Dn / 128, Mn / 128);
    gemm_mma_split<<<ggrid, 256, GEMM_SMEM>>>(hAhi, hAlo,
        Whi + 0 * (size_t)Dn * Dn, Wlo + 0 * (size_t)Dn * Dn, Qh, Ql, 0.125f);
    gemm_mma_split<<<ggrid, 256, GEMM_SMEM>>>(hAhi, hAlo,
        Whi + 1 * (size_t)Dn * Dn, Wlo + 1 * (size_t)Dn * Dn, Kh, Kl, 1.0f);
    gemm_mma_split<<<ggrid, 256, GEMM_SMEM>>>(hAhi, hAlo,
        Whi + 2 * (size_t)Dn * Dn, Wlo + 2 * (size_t)Dn * Dn, Vh, Vl, 1.0f);

    // Attention (tensorized flash)
    flash_mma<<<dim3(Sn / 64, Hn, Bn), 128, FLASH_SMEM>>>();

    // Output projection
    gemm_mma<<<ggrid, 256, GEMM_SMEM>>>(AVh, AVl,
        Whi + 3 * (size_t)Dn * Dn, Wlo + 3 * (size_t)Dn * Dn, AOp);

    ln_residual<<<Mn, 256>>>(h, gamma, beta, out);
}

// round 6
// speedup vs baseline: 2.8229x; 1.1436x over previous
#include <cuda_runtime.h>
#include <cuda_bf16.h>
#include <cstdint>
#include <math.h>

#define Bn 4
#define Sn 2048
#define Dn 1024
#define Hn 16
#define DHn 64
#define Mn (Bn * Sn)   // 8192

// ---------------------------------------------------------------------------
// Device scratch
// ---------------------------------------------------------------------------
__device__ float g_AO[Mn * Dn];

__device__ __nv_bfloat16 g_hA_hi[Mn * Dn];
__device__ __nv_bfloat16 g_hA_lo[Mn * Dn];
__device__ __nv_bfloat16 g_W_hi[4 * Dn * Dn];   // transposed [N,K], order q,k,v,o
__device__ __nv_bfloat16 g_W_lo[4 * Dn * Dn];

__device__ __nv_bfloat16 g_Qh[Mn * Dn];  // pre-scaled by 0.125
__device__ __nv_bfloat16 g_Ql[Mn * Dn];
__device__ __nv_bfloat16 g_Kh[Mn * Dn];
__device__ __nv_bfloat16 g_Kl[Mn * Dn];
__device__ __nv_bfloat16 g_Vh[Mn * Dn];
__device__ __nv_bfloat16 g_Vl[Mn * Dn];
__device__ __nv_bfloat16 g_AVh[Mn * Dn];
__device__ __nv_bfloat16 g_AVl[Mn * Dn];

// ---------------------------------------------------------------------------
__device__ __forceinline__ uint32_t smem_u32(const void* p) {
    uint32_t a;
    asm("{ .reg .u64 t; cvta.to.shared.u64 t, %1; cvt.u32.u64 %0, t; }"
        : "=r"(a) : "l"(p));
    return a;
}

__device__ __forceinline__ void ldm_x4(uint32_t* r, uint32_t addr) {
    asm volatile("ldmatrix.sync.aligned.m8n8.x4.shared.b16 {%0,%1,%2,%3}, [%4];"
                 : "=r"(r[0]), "=r"(r[1]), "=r"(r[2]), "=r"(r[3]) : "r"(addr));
}
__device__ __forceinline__ void ldm_x4t(uint32_t* r, uint32_t addr) {
    asm volatile("ldmatrix.sync.aligned.m8n8.x4.trans.shared.b16 {%0,%1,%2,%3}, [%4];"
                 : "=r"(r[0]), "=r"(r[1]), "=r"(r[2]), "=r"(r[3]) : "r"(addr));
}

__device__ __forceinline__ void mma_bf16(float* c, const uint32_t* a,
                                         uint32_t b0, uint32_t b1) {
    asm volatile(
        "mma.sync.aligned.m16n8k16.row.col.f32.bf16.bf16.f32 "
        "{%0,%1,%2,%3}, {%4,%5,%6,%7}, {%8,%9}, {%0,%1,%2,%3};"
        : "+f"(c[0]), "+f"(c[1]), "+f"(c[2]), "+f"(c[3])
        : "r"(a[0]), "r"(a[1]), "r"(a[2]), "r"(a[3]), "r"(b0), "r"(b1));
}

__device__ __forceinline__ uint32_t pack_bf16x2(float lo, float hi) {
    uint32_t d;
    asm("cvt.rn.bf16x2.f32 %0, %1, %2;" : "=r"(d) : "f"(hi), "f"(lo));
    return d;
}

__device__ __forceinline__ void cp16(uint32_t s, const void* g) {
    asm volatile("cp.async.cg.shared.global [%0], [%1], 16;" :: "r"(s), "l"(g));
}
#define CP_COMMIT() asm volatile("cp.async.commit_group;" ::: "memory")
#define CP_WAIT0()  asm volatile("cp.async.wait_group 0;" ::: "memory")

// ---------------------------------------------------------------------------
// Split fp32 -> (hi, lo) bf16 pair, elementwise.
// ---------------------------------------------------------------------------
__global__ __launch_bounds__(256) void split_f32(
    const float* __restrict__ x, __nv_bfloat16* __restrict__ hi,
    __nv_bfloat16* __restrict__ lo)
{
    const int i = (blockIdx.x * 256 + threadIdx.x) * 4;
    float4 v = *(const float4*)(x + i);
    __nv_bfloat16 h0 = __float2bfloat16(v.x);
    __nv_bfloat16 h1 = __float2bfloat16(v.y);
    __nv_bfloat16 h2 = __float2bfloat16(v.z);
    __nv_bfloat16 h3 = __float2bfloat16(v.w);
    __nv_bfloat16 l0 = __float2bfloat16(v.x - __bfloat162float(h0));
    __nv_bfloat16 l1 = __float2bfloat16(v.y - __bfloat162float(h1));
    __nv_bfloat16 l2 = __float2bfloat16(v.z - __bfloat162float(h2));
    __nv_bfloat16 l3 = __float2bfloat16(v.w - __bfloat162float(h3));
    __nv_bfloat162* hp = (__nv_bfloat162*)(hi + i);
    __nv_bfloat162* lp = (__nv_bfloat162*)(lo + i);
    hp[0] = __nv_bfloat162(h0, h1); hp[1] = __nv_bfloat162(h2, h3);
    lp[0] = __nv_bfloat162(l0, l1); lp[1] = __nv_bfloat162(l2, l3);
}

// ---------------------------------------------------------------------------
// Split + transpose: W fp32 [K=1024, N=1024] -> hi/lo bf16 [N, K]
// ---------------------------------------------------------------------------
__global__ __launch_bounds__(256) void split_T(
    const float* __restrict__ W, __nv_bfloat16* __restrict__ hiT,
    __nv_bfloat16* __restrict__ loT)
{
    __shared__ float t[32][33];
    const int tx = threadIdx.x, ty = threadIdx.y;
    const int bn = blockIdx.x * 32, bk = blockIdx.y * 32;
#pragma unroll
    for (int j = 0; j < 4; j++)
        t[ty + j * 8][tx] = W[(size_t)(bk + ty + j * 8) * Dn + bn + tx];
    __syncthreads();
#pragma unroll
    for (int j = 0; j < 4; j++) {
        float v = t[tx][ty + j * 8];
        __nv_bfloat16 h = __float2bfloat16(v);
        __nv_bfloat16 l = __float2bfloat16(v - __bfloat162float(h));
        size_t o = (size_t)(bn + ty + j * 8) * Dn + bk + tx;
        hiT[o] = h;
        loT[o] = l;
    }
}

// ---------------------------------------------------------------------------
// GEMM mainloop (mma.sync bf16-split, cp.async double buffer).
// EPI = 0: fp32 output C.  EPI = 1: hi/lo bf16 split output (scaled).
// 128x128 CTA tile, 8 warps (2M x 4N), 64x32 per warp, BK=32.
// ---------------------------------------------------------------------------
#define BK        32
#define NSTAGE    (Dn / BK)          // 32
#define ROW_B     80                 // bytes per smem row (32 bf16 + 8 pad)
#define ARR_SZ    (128 * ROW_B)      // 10240 bytes per array tile
#define BUF_SZ    (4 * ARR_SZ)
#define GEMM_SMEM (2 * BUF_SZ)       // 81920

template <int EPI>
__device__ __forceinline__ void gemm_body(
    const __nv_bfloat16* __restrict__ Ahi, const __nv_bfloat16* __restrict__ Alo,
    const __nv_bfloat16* __restrict__ Bhi, const __nv_bfloat16* __restrict__ Blo,
    float* __restrict__ C,
    __nv_bfloat16* __restrict__ Chi, __nv_bfloat16* __restrict__ Clo, float scale)
{
    extern __shared__ char smem[];
    const uint32_t sb = smem_u32(smem);
    const int tid  = threadIdx.x;
    const int wid  = tid >> 5;
    const int lane = tid & 31;
    const int m0 = blockIdx.y * 128;
    const int n0 = blockIdx.x * 128;
    const int m0w = (wid & 1) * 64;
    const int n0w = (wid >> 1) * 32;

    const char* src[4] = {(const char*)Ahi, (const char*)Alo,
                          (const char*)Bhi, (const char*)Blo};

    const int r0c = tid >> 2;
    const int c16 = tid & 3;
    size_t goff[4][2];
#pragma unroll
    for (int arr = 0; arr < 4; arr++) {
        const int tb = (arr < 2) ? m0 : n0;
#pragma unroll
        for (int it = 0; it < 2; it++)
            goff[arr][it] = (size_t)(tb + r0c + it * 64) * 2048 + c16 * 16;
    }
    const uint32_t soff0 = r0c * ROW_B + c16 * 16;
    const uint32_t soff1 = (r0c + 64) * ROW_B + c16 * 16;

    float acc[4][4][4];
#pragma unroll
    for (int i = 0; i < 4; i++)
#pragma unroll
        for (int j = 0; j < 4; j++)
#pragma unroll
            for (int k = 0; k < 4; k++) acc[i][j][k] = 0.f;

    const int lrow = lane & 15;
    const int lch  = lane >> 4;
    const uint32_t a_lbase = (uint32_t)(m0w + lrow) * ROW_B + lch * 16;
    const uint32_t b_lbase = (uint32_t)(n0w + lrow) * ROW_B + lch * 16;

    // Preload stage 0 via cp.async
#pragma unroll
    for (int arr = 0; arr < 4; arr++) {
        cp16(sb + arr * ARR_SZ + soff0, src[arr] + goff[arr][0]);
        cp16(sb + arr * ARR_SZ + soff1, src[arr] + goff[arr][1]);
    }
    CP_COMMIT();
    CP_WAIT0();
    __syncthreads();

    for (int kc = 0; kc < NSTAGE; kc++) {
        const int cb = kc & 1;

        // Prefetch next stage into other buffer (overlaps with compute below)
        if (kc + 1 < NSTAGE) {
            const size_t kb = (size_t)(kc + 1) * 64;
            const uint32_t db = sb + (cb ^ 1) * BUF_SZ;
#pragma unroll
            for (int arr = 0; arr < 4; arr++) {
                cp16(db + arr * ARR_SZ + soff0, src[arr] + goff[arr][0] + kb);
                cp16(db + arr * ARR_SZ + soff1, src[arr] + goff[arr][1] + kb);
            }
            CP_COMMIT();
        }

        const uint32_t bufb = sb + cb * BUF_SZ;
#pragma unroll
        for (int ks = 0; ks < 2; ks++) {
#pragma unroll
            for (int t = 0; t < 3; t++) {
                const int aArr = (t == 2) ? 1 : 0;
                const int bArr = (t == 1) ? 3 : 2;
                uint32_t afr[4][4];
#pragma unroll
                for (int mi = 0; mi < 4; mi++)
                    ldm_x4(afr[mi], bufb + aArr * ARR_SZ + a_lbase
                                      + mi * (16 * ROW_B) + ks * 32);
                uint32_t bfr[2][4];
#pragma unroll
                for (int ni = 0; ni < 2; ni++)
                    ldm_x4(bfr[ni], bufb + bArr * ARR_SZ + b_lbase
                                      + ni * (16 * ROW_B) + ks * 32);
#pragma unroll
                for (int mi = 0; mi < 4; mi++) {
#pragma unroll
                    for (int ni = 0; ni < 2; ni++) {
                        mma_bf16(acc[mi][ni * 2 + 0], afr[mi], bfr[ni][0], bfr[ni][2]);
                        mma_bf16(acc[mi][ni * 2 + 1], afr[mi], bfr[ni][1], bfr[ni][3]);
                    }
                }
            }
        }

        CP_WAIT0();
        __syncthreads();
    }

    // Epilogue
    const int erow = lane >> 2;
    const int ecol = (lane & 3) * 2;
#pragma unroll
    for (int mi = 0; mi < 4; mi++) {
#pragma unroll
        for (int nj = 0; nj < 4; nj++) {
            size_t base0 = (size_t)(m0 + m0w + mi * 16 + erow) * Dn
                         + n0 + n0w + nj * 8 + ecol;
            if (EPI == 0) {
                *(float2*)(C + base0)          = make_float2(acc[mi][nj][0], acc[mi][nj][1]);
                *(float2*)(C + base0 + 8 * Dn) = make_float2(acc[mi][nj][2], acc[mi][nj][3]);
            } else {
#pragma unroll
                for (int half = 0; half < 2; half++) {
                    size_t b = base0 + half * 8 * Dn;
                    float v0 = acc[mi][nj][half * 2 + 0] * scale;
                    float v1 = acc[mi][nj][half * 2 + 1] * scale;
                    __nv_bfloat16 h0 = __float2bfloat16(v0);
                    __nv_bfloat16 h1 = __float2bfloat16(v1);
                    __nv_bfloat16 l0 = __float2bfloat16(v0 - __bfloat162float(h0));
                    __nv_bfloat16 l1 = __float2bfloat16(v1 - __bfloat162float(h1));
                    *(__nv_bfloat162*)(Chi + b) = __nv_bfloat162(h0, h1);
                    *(__nv_bfloat162*)(Clo + b) = __nv_bfloat162(l0, l1);
                }
            }
        }
    }
}

__global__ __launch_bounds__(256, 1) void gemm_mma(
    const __nv_bfloat16* __restrict__ Ahi, const __nv_bfloat16* __restrict__ Alo,
    const __nv_bfloat16* __restrict__ Bhi, const __nv_bfloat16* __restrict__ Blo,
    float* __restrict__ C)
{
    gemm_body<0>(Ahi, Alo, Bhi, Blo, C, nullptr, nullptr, 1.0f);
}

__global__ __launch_bounds__(256, 1) void gemm_mma_split(
    const __nv_bfloat16* __restrict__ Ahi, const __nv_bfloat16* __restrict__ Alo,
    const __nv_bfloat16* __restrict__ Bhi, const __nv_bfloat16* __restrict__ Blo,
    __nv_bfloat16* __restrict__ Chi, __nv_bfloat16* __restrict__ Clo, float scale)
{
    gemm_body<1>(Ahi, Alo, Bhi, Blo, nullptr, Chi, Clo, scale);
}

// ---------------------------------------------------------------------------
// Flash attention on mma.sync bf16 with hi/lo splits.
// Grid (16, 16, 4): 128 q-rows per CTA, 256 threads (8 warps x m16).
// K/V tiles (64 keys) double-buffered via cp.async.
// ---------------------------------------------------------------------------
#define FROW 144
#define FARR (64 * FROW)          // 9216 (one 64x64 bf16 tile)
#define QARR (128 * FROW)         // 18432 (one 128x64 bf16 tile)
#define KVBUF (4 * FARR)          // Kh,Kl,Vh,Vl
#define FLASH_SMEM (2 * QARR + 2 * KVBUF)   // 110592

__global__ __launch_bounds__(256) void flash_mma()
{
    extern __shared__ char sm[];
    const uint32_t sb = smem_u32(sm);
    const int tid = threadIdx.x;
    const int lane = tid & 31;
    const int w = tid >> 5;
    const int qt = blockIdx.x, hh = blockIdx.y, bb = blockIdx.z;

    const size_t headoff = (size_t)hh * 64;

    // Load Q hi/lo tiles (128 x 64 bf16 each), plain stores
#pragma unroll
    for (int i = 0; i < 4; i++) {
        const int idx = tid + 256 * i;              // 0..1023
        const int r = idx >> 3, ch = idx & 7;
        const size_t g = (size_t)(bb * Sn + qt * 128 + r) * Dn + headoff + ch * 8;
        const uint32_t so = r * FROW + ch * 16;
        *(uint4*)(sm + so)        = *(const uint4*)(g_Qh + g);
        *(uint4*)(sm + QARR + so) = *(const uint4*)(g_Ql + g);
    }

    const int lrow = lane & 15;
    const int lch  = lane >> 4;
    const uint32_t aoff = (uint32_t)(w * 16 + lrow) * FROW + lch * 16;     // Q (A)
    uint32_t boff[4];
#pragma unroll
    for (int np = 0; np < 4; np++)
        boff[np] = (uint32_t)(np * 16 + lrow) * FROW + lch * 16;           // K (B)

    // K/V cp.async loader: 512 16B-chunks per array, 2 per thread
    const int kr0 = tid >> 3;           // rows 0..31
    const int kch = tid & 7;
    const uint32_t kso0 = (uint32_t)kr0 * FROW + kch * 16;
    const uint32_t kso1 = (uint32_t)(kr0 + 32) * FROW + kch * 16;

    float o[8][4];
#pragma unroll
    for (int j = 0; j < 8; j++)
#pragma unroll
        for (int k = 0; k < 4; k++) o[j][k] = 0.f;
    float m0r = -1e30f, m1r = -1e30f, l0r = 0.f, l1r = 0.f;

    // preload kt=0 into buffer 0
    {
        const uint32_t base = sb + 2 * QARR;
        const size_t g0 = (size_t)(bb * Sn + kr0) * Dn + headoff + kch * 8;
        const size_t g1 = g0 + (size_t)32 * Dn;
        cp16(base + 0 * FARR + kso0, g_Kh + g0);
        cp16(base + 0 * FARR + kso1, g_Kh + g1);
        cp16(base + 1 * FARR + kso0, g_Kl + g0);
        cp16(base + 1 * FARR + kso1, g_Kl + g1);
        cp16(base + 2 * FARR + kso0, g_Vh + g0);
        cp16(base + 2 * FARR + kso1, g_Vh + g1);
        cp16(base + 3 * FARR + kso0, g_Vl + g0);
        cp16(base + 3 * FARR + kso1, g_Vl + g1);
        CP_COMMIT();
    }

    for (int kt = 0; kt < Sn / 64; kt++) {
        const int buf = kt & 1;
        CP_WAIT0();
        __syncthreads();

        // prefetch next tile into the other buffer (overlaps compute)
        if (kt + 1 < Sn / 64) {
            const uint32_t base = sb + 2 * QARR + (buf ^ 1) * KVBUF;
            const size_t g0 = (size_t)(bb * Sn + (kt + 1) * 64 + kr0) * Dn
                            + headoff + kch * 8;
            const size_t g1 = g0 + (size_t)32 * Dn;
            cp16(base + 0 * FARR + kso0, g_Kh + g0);
            cp16(base + 0 * FARR + kso1, g_Kh + g1);
            cp16(base + 1 * FARR + kso0, g_Kl + g0);
            cp16(base + 1 * FARR + kso1, g_Kl + g1);
            cp16(base + 2 * FARR + kso0, g_Vh + g0);
            cp16(base + 2 * FARR + kso1, g_Vh + g1);
            cp16(base + 3 * FARR + kso0, g_Vl + g0);
            cp16(base + 3 * FARR + kso1, g_Vl + g1);
            CP_COMMIT();
        }

        const uint32_t kvb = sb + 2 * QARR + buf * KVBUF;

        // ---- S = Q*K^T (3 split terms), n=64 keys ----
        float s[8][4];
#pragma unroll
        for (int j = 0; j < 8; j++)
#pragma unroll
            for (int k = 0; k < 4; k++) s[j][k] = 0.f;

#pragma unroll
        for (int ks = 0; ks < 4; ks++) {
            uint32_t qh[4], ql[4];
            ldm_x4(qh, sb + aoff + ks * 32);
            ldm_x4(ql, sb + QARR + aoff + ks * 32);
#pragma unroll
            for (int np = 0; np < 4; np++) {
                uint32_t kh[4], kl[4];
                ldm_x4(kh, kvb + 0 * FARR + boff[np] + ks * 32);
                ldm_x4(kl, kvb + 1 * FARR + boff[np] + ks * 32);
                mma_bf16(s[2 * np + 0], qh, kh[0], kh[2]);
                mma_bf16(s[2 * np + 1], qh, kh[1], kh[3]);
                mma_bf16(s[2 * np + 0], qh, kl[0], kl[2]);
                mma_bf16(s[2 * np + 1], qh, kl[1], kl[3]);
                mma_bf16(s[2 * np + 0], ql, kh[0], kh[2]);
                mma_bf16(s[2 * np + 1], ql, kh[1], kh[3]);
            }
        }

        // ---- Online softmax (rows lane/4 and lane/4+8 within warp tile) ----
        float mx0 = -1e30f, mx1 = -1e30f;
#pragma unroll
        for (int j = 0; j < 8; j++) {
            mx0 = fmaxf(mx0, fmaxf(s[j][0], s[j][1]));
            mx1 = fmaxf(mx1, fmaxf(s[j][2], s[j][3]));
        }
        mx0 = fmaxf(mx0, __shfl_xor_sync(0xffffffffu, mx0, 1));
        mx0 = fmaxf(mx0, __shfl_xor_sync(0xffffffffu, mx0, 2));
        mx1 = fmaxf(mx1, __shfl_xor_sync(0xffffffffu, mx1, 1));
        mx1 = fmaxf(mx1, __shfl_xor_sync(0xffffffffu, mx1, 2));

        const float mn0 = fmaxf(m0r, mx0);
        const float mn1 = fmaxf(m1r, mx1);
        const float a0 = __expf(m0r - mn0);
        const float a1 = __expf(m1r - mn1);
        m0r = mn0; m1r = mn1;

        uint32_t phi[8][2], plo[8][2];
        float sum0 = 0.f, sum1 = 0.f;
#pragma unroll
        for (int j = 0; j < 8; j++) {
            float p00 = __expf(s[j][0] - mn0);
            float p01 = __expf(s[j][1] - mn0);
            float p10 = __expf(s[j][2] - mn1);
            float p11 = __expf(s[j][3] - mn1);
            sum0 += p00 + p01;
            sum1 += p10 + p11;
            __nv_bfloat16 h00 = __float2bfloat16(p00);
            __nv_bfloat16 h01 = __float2bfloat16(p01);
            __nv_bfloat16 h10 = __float2bfloat16(p10);
            __nv_bfloat16 h11 = __float2bfloat16(p11);
            phi[j][0] = ((uint32_t)__bfloat16_as_ushort(h01) << 16)
                      |  (uint32_t)__bfloat16_as_ushort(h00);
            phi[j][1] = ((uint32_t)__bfloat16_as_ushort(h11) << 16)
                      |  (uint32_t)__bfloat16_as_ushort(h10);
            plo[j][0] = pack_bf16x2(p00 - __bfloat162float(h00),
                                    p01 - __bfloat162float(h01));
            plo[j][1] = pack_bf16x2(p10 - __bfloat162float(h10),
                                    p11 - __bfloat162float(h11));
        }
        sum0 += __shfl_xor_sync(0xffffffffu, sum0, 1);
        sum0 += __shfl_xor_sync(0xffffffffu, sum0, 2);
        sum1 += __shfl_xor_sync(0xffffffffu, sum1, 1);
        sum1 += __shfl_xor_sync(0xffffffffu, sum1, 2);
        l0r = l0r * a0 + sum0;
        l1r = l1r * a1 + sum1;

#pragma unroll
        for (int j = 0; j < 8; j++) {
            o[j][0] *= a0; o[j][1] *= a0;
            o[j][2] *= a1; o[j][3] *= a1;
        }

        // ---- O += P * V (3 split terms), V via ldmatrix.trans ----
#pragma unroll
        for (int ks = 0; ks < 4; ks++) {
            uint32_t ah[4] = {phi[2 * ks][0], phi[2 * ks][1],
                              phi[2 * ks + 1][0], phi[2 * ks + 1][1]};
            uint32_t al[4] = {plo[2 * ks][0], plo[2 * ks][1],
                              plo[2 * ks + 1][0], plo[2 * ks + 1][1]};
            const uint32_t vbase = (uint32_t)(ks * 16 + lrow) * FROW + lch * 16;
#pragma unroll
            for (int np = 0; np < 4; np++) {
                uint32_t vh[4], vl[4];
                ldm_x4t(vh, kvb + 2 * FARR + vbase + np * 32);
                ldm_x4t(vl, kvb + 3 * FARR + vbase + np * 32);
                mma_bf16(o[2 * np + 0], ah, vh[0], vh[1]);
                mma_bf16(o[2 * np + 1], ah, vh[2], vh[3]);
                mma_bf16(o[2 * np + 0], al, vh[0], vh[1]);
                mma_bf16(o[2 * np + 1], al, vh[2], vh[3]);
                mma_bf16(o[2 * np + 0], ah, vl[0], vl[1]);
                mma_bf16(o[2 * np + 1], ah, vl[2], vl[3]);
            }
        }
        __syncthreads();   // all warps done reading buf before next prefetch lands
    }

    // Epilogue: normalize, split to hi/lo bf16, write AV
    const float inv0 = 1.0f / l0r;
    const float inv1 = 1.0f / l1r;
    const size_t row0 = (size_t)(bb * Sn + qt * 128 + w * 16 + (lane >> 2));
    const size_t row1 = row0 + 8;
    const size_t colb = headoff + (lane & 3) * 2;
#pragma unroll
    for (int j = 0; j < 8; j++) {
        float v0 = o[j][0] * inv0, v1 = o[j][1] * inv0;
        float v2 = o[j][2] * inv1, v3 = o[j][3] * inv1;
        __nv_bfloat16 h0 = __float2bfloat16(v0);
        __nv_bfloat16 h1 = __float2bfloat16(v1);
        __nv_bfloat16 h2 = __float2bfloat16(v2);
        __nv_bfloat16 h3 = __float2bfloat16(v3);
        size_t b0 = row0 * Dn + colb + j * 8;
        size_t b1 = row1 * Dn + colb + j * 8;
        *(__nv_bfloat162*)(g_AVh + b0) = __nv_bfloat162(h0, h1);
        *(__nv_bfloat162*)(g_AVh + b1) = __nv_bfloat162(h2, h3);
        *(__nv_bfloat162*)(g_AVl + b0) =
            __nv_bfloat162(__float2bfloat16(v0 - __bfloat162float(h0)),
                           __float2bfloat16(v1 - __bfloat162float(h1)));
        *(__nv_bfloat162*)(g_AVl + b1) =
            __nv_bfloat162(__float2bfloat16(v2 - __bfloat162float(h2)),
                           __float2bfloat16(v3 - __bfloat162float(h3)));
    }
}

// ---------------------------------------------------------------------------
// Residual + LayerNorm
// ---------------------------------------------------------------------------
__global__ __launch_bounds__(256) void ln_residual(
    const float* __restrict__ h, const float* __restrict__ gamma,
    const float* __restrict__ beta, float* __restrict__ out)
{
    const int row = blockIdx.x;
    const int tid = threadIdx.x;

    const float4 hv = *(const float4*)(h + row * Dn + tid * 4);
    const float4 av = *(const float4*)(g_AO + row * Dn + tid * 4);
    float4 x = make_float4(hv.x + av.x, hv.y + av.y, hv.z + av.z, hv.w + av.w);

    float s  = x.x + x.y + x.z + x.w;
    float ss = x.x * x.x + x.y * x.y + x.z * x.z + x.w * x.w;
#pragma unroll
    for (int off = 16; off > 0; off >>= 1) {
        s  += __shfl_xor_sync(0xffffffffu, s, off);
        ss += __shfl_xor_sync(0xffffffffu, ss, off);
    }
    __shared__ float rs[8], rss[8];
    if ((tid & 31) == 0) { rs[tid >> 5] = s; rss[tid >> 5] = ss; }
    __syncthreads();
    s = 0.f; ss = 0.f;
#pragma unroll
    for (int w = 0; w < 8; w++) { s += rs[w]; ss += rss[w]; }

    const float mu  = s * (1.0f / Dn);
    const float var = ss * (1.0f / Dn) - mu * mu;
    const float inv = rsqrtf(var + 1e-5f);

    const float4 g4 = *(const float4*)(gamma + tid * 4);
    const float4 b4 = *(const float4*)(beta + tid * 4);
    float4 r;
    r.x = g4.x * (x.x - mu) * inv + b4.x;
    r.y = g4.y * (x.y - mu) * inv + b4.y;
    r.z = g4.z * (x.z - mu) * inv + b4.z;
    r.w = g4.w * (x.w - mu) * inv + b4.w;
    *(float4*)(out + row * Dn + tid * 4) = r;
}

// ---------------------------------------------------------------------------
extern "C" void kernel_launch(void* const* d_in, const int* in_sizes, int n_in,
                              void* d_out, int out_size)
{
    (void)in_sizes; (void)n_in; (void)out_size;
    const float* h     = (const float*)d_in[0];
    const float* Wq    = (const float*)d_in[1];
    const float* Wk    = (const float*)d_in[2];
    const float* Wv    = (const float*)d_in[3];
    const float* Wo    = (const float*)d_in[4];
    const float* gamma = (const float*)d_in[5];
    const float* beta  = (const float*)d_in[6];
    float* out = (float*)d_out;

    float* AOp;
    __nv_bfloat16 *hAhi, *hAlo, *Whi, *Wlo;
    __nv_bfloat16 *Qh, *Ql, *Kh, *Kl, *Vh, *Vl, *AVh, *AVl;
    cudaGetSymbolAddress((void**)&AOp,  g_AO);
    cudaGetSymbolAddress((void**)&hAhi, g_hA_hi);
    cudaGetSymbolAddress((void**)&hAlo, g_hA_lo);
    cudaGetSymbolAddress((void**)&Whi,  g_W_hi);
    cudaGetSymbolAddress((void**)&Wlo,  g_W_lo);
    cudaGetSymbolAddress((void**)&Qh,   g_Qh);
    cudaGetSymbolAddress((void**)&Ql,   g_Ql);
    cudaGetSymbolAddress((void**)&Kh,   g_Kh);
    cudaGetSymbolAddress((void**)&Kl,   g_Kl);
    cudaGetSymbolAddress((void**)&Vh,   g_Vh);
    cudaGetSymbolAddress((void**)&Vl,   g_Vl);
    cudaGetSymbolAddress((void**)&AVh,  g_AVh);
    cudaGetSymbolAddress((void**)&AVl,  g_AVl);

    cudaFuncSetAttribute(gemm_mma, cudaFuncAttributeMaxDynamicSharedMemorySize,
                         GEMM_SMEM);
    cudaFuncSetAttribute(gemm_mma_split, cudaFuncAttributeMaxDynamicSharedMemorySize,
                         GEMM_SMEM);
    cudaFuncSetAttribute(flash_mma, cudaFuncAttributeMaxDynamicSharedMemorySize,
                         FLASH_SMEM);

    // Split h and weights into bf16 hi/lo
    split_f32<<<Mn * Dn / 1024, 256>>>(h, hAhi, hAlo);
    dim3 tgrid(32, 32), tblk(32, 8);
    split_T<<<tgrid, tblk>>>(Wq, Whi + 0 * (size_t)Dn * Dn, Wlo + 0 * (size_t)Dn * Dn);
    split_T<<<tgrid, tblk>>>(Wk, Whi + 1 * (size_t)Dn * Dn, Wlo + 1 * (size_t)Dn * Dn);
    split_T<<<tgrid, tblk>>>(Wv, Whi + 2 * (size_t)Dn * Dn, Wlo + 2 * (size_t)Dn * Dn);
    split_T<<<tgrid, tblk>>>(Wo, Whi + 3 * (size_t)Dn * Dn, Wlo + 3 * (size_t)Dn * Dn);

    // Q/K/V projections -> hi/lo bf16 (Q pre-scaled by 1/8)
    dim3 ggrid(Dn / 128, Mn / 128);
    gemm_mma_split<<<ggrid, 256, GEMM_SMEM>>>(hAhi, hAlo,
        Whi + 0 * (size_t)Dn * Dn, Wlo + 0 * (size_t)Dn * Dn, Qh, Ql, 0.125f);
    gemm_mma_split<<<ggrid, 256, GEMM_SMEM>>>(hAhi, hAlo,
        Whi + 1 * (size_t)Dn * Dn, Wlo + 1 * (size_t)Dn * Dn, Kh, Kl, 1.0f);
    gemm_mma_split<<<ggrid, 256, GEMM_SMEM>>>(hAhi, hAlo,
        Whi + 2 * (size_t)Dn * Dn, Wlo + 2 * (size_t)Dn * Dn, Vh, Vl, 1.0f);

    // Attention (tensorized flash, 128-row q tiles, cp.async pipelined)
    flash_mma<<<dim3(Sn / 128, Hn, Bn), 256, FLASH_SMEM>>>();

    // Output projection
    gemm_mma<<<ggrid, 256, GEMM_SMEM>>>(AVh, AVl,
        Whi + 3 * (size_t)Dn * Dn, Wlo + 3 * (size_t)Dn * Dn, AOp);

    ln_residual<<<Mn, 256>>>(h, gamma, beta, out);
}